// round 6
// baseline (speedup 1.0000x reference)
#include <cuda_runtime.h>
#include <math.h>
#include <cstdint>

#define BB    2048
#define NN    62
#define FIN   128
#define HID   512
#define HEADS 8
#define FOUT  64
#define NROWS (BB * NN)   // 126976

// Scratch: features ping-pong between g_hx and g_h; g_Wr = tf32-rounded W_gat.
__device__ float g_hx[(size_t)NROWS * HID];
__device__ float g_h [(size_t)NROWS * HID];
__device__ float g_Wr[(size_t)3 * HEADS * HID * FOUT];

// ===========================================================================
// helpers
// ===========================================================================
__device__ __forceinline__ uint32_t smem_u32(const void* p) {
    uint32_t a;
    asm("{ .reg .u64 t; cvta.to.shared.u64 t, %1; cvt.u32.u64 %0, t; }"
        : "=r"(a) : "l"(p));
    return a;
}
__device__ __forceinline__ float tf32r(float x) {
    uint32_t u;
    asm("cvt.rna.tf32.f32 %0, %1;" : "=r"(u) : "f"(x));
    return __uint_as_float(u);
}
__device__ __forceinline__ void cp_async16(uint32_t dst, const void* src) {
    asm volatile("cp.async.cg.shared.global [%0], [%1], 16;"
                 :: "r"(dst), "l"(src) : "memory");
}
__device__ __forceinline__ void cp_commit() {
    asm volatile("cp.async.commit_group;" ::: "memory");
}
template <int N>
__device__ __forceinline__ void cp_wait() {
    asm volatile("cp.async.wait_group %0;" :: "n"(N) : "memory");
}
__device__ __forceinline__ void mma_tf32(float* c, const uint32_t* a, const uint32_t* b) {
    asm volatile(
        "mma.sync.aligned.m16n8k8.row.col.f32.tf32.tf32.f32 "
        "{%0,%1,%2,%3}, {%4,%5,%6,%7}, {%8,%9}, {%0,%1,%2,%3};"
        : "+f"(c[0]), "+f"(c[1]), "+f"(c[2]), "+f"(c[3])
        : "r"(a[0]), "r"(a[1]), "r"(a[2]), "r"(a[3]), "r"(b[0]), "r"(b[1]));
}

// ===========================================================================
// K0: round W_gat to tf32 (round-to-nearest) once per launch
// ===========================================================================
__global__ void k0_round_w(const float* __restrict__ Wg) {
    int i = blockIdx.x * 1024 + threadIdx.x;
    if (i < 3 * HEADS * HID * FOUT) g_Wr[i] = tf32r(Wg[i]);
}

// ===========================================================================
// K1: fused BatchNorm + input MLP (output rounded to tf32 for K2)
// ===========================================================================
__global__ __launch_bounds__(128) void k1_bn_mlp(
    const float* __restrict__ x,
    const float* __restrict__ gamma, const float* __restrict__ beta,
    const float* __restrict__ mean,  const float* __restrict__ var,
    const float* __restrict__ Wm,    const float* __restrict__ bm)
{
    __shared__ float xs[8][FIN];
    int row0 = blockIdx.x * 8;

    for (int idx = threadIdx.x; idx < 8 * FIN; idx += 128) {
        int r = idx >> 7, k = idx & 127;
        int row = row0 + r;
        int n = row % NN;
        float sc = gamma[n] * rsqrtf(var[n] + 1e-5f);
        xs[r][k] = (x[(size_t)row * FIN + k] - mean[n]) * sc + beta[n];
    }
    __syncthreads();

    int col = threadIdx.x * 4;
    float acc[8][4];
#pragma unroll
    for (int r = 0; r < 8; r++)
#pragma unroll
        for (int c = 0; c < 4; c++) acc[r][c] = 0.f;

#pragma unroll 4
    for (int k = 0; k < FIN; k++) {
        float4 w = *(const float4*)(Wm + (size_t)k * HID + col);
#pragma unroll
        for (int r = 0; r < 8; r++) {
            float xv = xs[r][k];
            acc[r][0] += xv * w.x;
            acc[r][1] += xv * w.y;
            acc[r][2] += xv * w.z;
            acc[r][3] += xv * w.w;
        }
    }

    float4 bv = *(const float4*)(bm + col);
#pragma unroll
    for (int r = 0; r < 8; r++) {
        float4 o = make_float4(tf32r(acc[r][0] + bv.x), tf32r(acc[r][1] + bv.y),
                               tf32r(acc[r][2] + bv.z), tf32r(acc[r][3] + bv.w));
        *(float4*)&g_hx[(size_t)(row0 + r) * HID + col] = o;
    }
}

// ===========================================================================
// K2 (tf32 mma.sync): g_h = g_hx @ W_gat[l]   [126976 x 512] @ [512 x 512]
// CTA 256 thr, tile 128x128. cp.async 4-stage pipeline, KC=32 per stage.
// ===========================================================================
#define TM 128
#define TN 128
#define KC 32
#define NS (HID / KC)     // 16
#define NBUF 4
#define A_STRIDE 36
#define B_STRIDE 136
#define A_BYTES (TM * A_STRIDE * 4)        // 18432
#define B_BYTES (KC * B_STRIDE * 4)        // 17408
#define STAGE_BYTES (A_BYTES + B_BYTES)    // 35840
#define K2_SMEM (NBUF * STAGE_BYTES)       // 143360

__global__ __launch_bounds__(256, 1) void k2_mma(int layer)
{
    extern __shared__ __align__(16) char smem[];
    const int tid  = threadIdx.x;
    const int lane = tid & 31;
    const int wid  = tid >> 5;
    const int wm   = wid & 3;     // 4 warps along M
    const int wn   = wid >> 2;    // 2 warps along N
    const int n0   = blockIdx.x * TN;     // col tile FAST grid dim (L2 reuse of A)
    const int row0 = blockIdx.y * TM;
    const uint32_t sbase = smem_u32(smem);
    const float* Wl = g_Wr + (size_t)layer * HEADS * HID * FOUT;
    const float* Wb = Wl + (size_t)(n0 >> 6) * HID * FOUT;

    auto issue_stage = [&](int s) {
        const int p = s & (NBUF - 1);
        const float* Ag = g_hx + (size_t)row0 * HID + s * KC;
        const uint32_t Ad = sbase + p * STAGE_BYTES;
#pragma unroll
        for (int i = 0; i < 4; i++) {
            int idx = tid + i * 256;          // 0..1023
            int r = idx >> 3, k4 = idx & 7;
            cp_async16(Ad + r * (A_STRIDE * 4) + k4 * 16,
                       Ag + (size_t)r * HID + k4 * 4);
        }
        const uint32_t Bd = sbase + p * STAGE_BYTES + A_BYTES;
#pragma unroll
        for (int i = 0; i < 4; i++) {
            int idx = tid + i * 256;          // 0..1023
            int k = idx >> 5, n4 = idx & 31;
            int n = n4 * 4;
            const float* sp = Wb + (size_t)(n >> 6) * HID * FOUT
                                 + (size_t)(s * KC + k) * FOUT + (n & 63);
            cp_async16(Bd + k * (B_STRIDE * 4) + n4 * 16, sp);
        }
    };

    float acc[2][8][4];
#pragma unroll
    for (int mt = 0; mt < 2; mt++)
#pragma unroll
        for (int nt = 0; nt < 8; nt++)
#pragma unroll
            for (int q = 0; q < 4; q++) acc[mt][nt][q] = 0.f;

#pragma unroll
    for (int s = 0; s < NBUF - 1; s++) { issue_stage(s); cp_commit(); }

#pragma unroll 1
    for (int s = 0; s < NS; s++) {
        if (s < NS - 2)       cp_wait<2>();
        else if (s == NS - 2) cp_wait<1>();
        else                  cp_wait<0>();
        __syncthreads();
        if (s + NBUF - 1 < NS) issue_stage(s + NBUF - 1);
        cp_commit();   // uniform group accounting

        const float* As = (const float*)(smem + (s & (NBUF - 1)) * STAGE_BYTES);
        const float* Bs = As + TM * A_STRIDE;

#pragma unroll
        for (int ks = 0; ks < KC / 8; ks++) {
            const int kb = ks * 8;
            uint32_t a[2][4], b[8][2];
#pragma unroll
            for (int mt = 0; mt < 2; mt++) {
                int r = wm * 32 + mt * 16 + (lane >> 2);
                int k = kb + (lane & 3);
                a[mt][0] = __float_as_uint(As[r * A_STRIDE + k]);
                a[mt][1] = __float_as_uint(As[(r + 8) * A_STRIDE + k]);
                a[mt][2] = __float_as_uint(As[r * A_STRIDE + k + 4]);
                a[mt][3] = __float_as_uint(As[(r + 8) * A_STRIDE + k + 4]);
            }
#pragma unroll
            for (int nt = 0; nt < 8; nt++) {
                int c = wn * 64 + nt * 8 + (lane >> 2);
                int k = kb + (lane & 3);
                b[nt][0] = __float_as_uint(Bs[k * B_STRIDE + c]);
                b[nt][1] = __float_as_uint(Bs[(k + 4) * B_STRIDE + c]);
            }
#pragma unroll
            for (int mt = 0; mt < 2; mt++)
#pragma unroll
                for (int nt = 0; nt < 8; nt++)
                    mma_tf32(acc[mt][nt], a[mt], b[nt]);
        }
    }

#pragma unroll
    for (int mt = 0; mt < 2; mt++) {
        int r = row0 + wm * 32 + mt * 16 + (lane >> 2);
#pragma unroll
        for (int nt = 0; nt < 8; nt++) {
            int c = n0 + wn * 64 + nt * 8 + 2 * (lane & 3);
            *(float2*)&g_h[(size_t)r * HID + c] =
                make_float2(acc[mt][nt][0], acc[mt][nt][1]);
            *(float2*)&g_h[(size_t)(r + 8) * HID + c] =
                make_float2(acc[mt][nt][2], acc[mt][nt][3]);
        }
    }
}

// ===========================================================================
// K4: per-(batch, head) attention. LDS-optimized:
//  - no max pass (values bounded; masked -> exp(-9e15)=0 exactly)
//  - 1/colsum folded into hs rows (one float4 pass) instead of es rescale
//  - aggregation: thread = (row i, d-quarter t): 1 scalar es + 4 LDS.128 hs
//    + 16 FFMA per j  (was 17 scalar LDS per 16 FFMA)
// ===========================================================================
__global__ __launch_bounds__(256) void k4_attn(
    const int* __restrict__ adj, const float* __restrict__ a_l)
{
    __shared__ float hs[64][68];          // stride 68 floats = 16B-aligned rows
    __shared__ float es[64][63];
    __shared__ float asv[2 * FOUT];
    __shared__ float f1[64], f2[64];
    __shared__ float ps[4][64];
    __shared__ float rsv[64];

    const int b    = blockIdx.x;
    const int head = blockIdx.y;
    const int tid  = threadIdx.x;

    const float* hbase = &g_h[(size_t)b * NN * HID + head * FOUT];
    // hs load: 62 rows x 16 float4
    for (int idx = tid; idx < NN * 16; idx += 256) {
        int j = idx >> 4, d4 = idx & 15;
        *(float4*)&hs[j][d4 * 4] =
            *(const float4*)(hbase + (size_t)j * HID + d4 * 4);
    }
    if (tid < 2 * FOUT) asv[tid] = a_l[head * 2 * FOUT + tid];
    if (tid < 136) hs[62 + tid / 68][tid % 68] = 0.f;   // zero pad rows 62,63
    __syncthreads();

    // f1/f2: 4 threads per node, quad shfl reduce (pad nodes produce 0)
    {
        int node = tid >> 2, t = tid & 3;
        float s1 = 0.f, s2 = 0.f;
#pragma unroll
        for (int dd = 0; dd < 16; dd++) {
            int d = t * 16 + dd;
            float v = hs[node][d];
            s1 += v * asv[d];
            s2 += v * asv[FOUT + d];
        }
        s1 += __shfl_xor_sync(0xffffffffu, s1, 1);
        s1 += __shfl_xor_sync(0xffffffffu, s1, 2);
        s2 += __shfl_xor_sync(0xffffffffu, s2, 1);
        s2 += __shfl_xor_sync(0xffffffffu, s2, 2);
        if (t == 0) { f1[node] = s1; f2[node] = s2; }
    }
    __syncthreads();

    // es[i][j] = exp(leaky(f2[i]+f1[j])) if adj else 0   (no max subtraction)
    const int* adjb = adj + (size_t)b * NN * NN;
    for (int idx = tid; idx < NN * NN; idx += 256) {
        int i = idx / NN, j = idx - i * NN;
        float v = f2[i] + f1[j];
        v = v > 0.f ? v : 0.2f * v;
        es[i][j] = (adjb[idx] > 0) ? __expf(v) : 0.f;
    }
    __syncthreads();

    // column sums (softmax over i)
    {
        int j = tid & 63, q = tid >> 6;
        float s = 0.f;
        if (j < NN) {
#pragma unroll
            for (int ii = 0; ii < 16; ii++) {
                int i = q + ii * 4;
                if (i < NN) s += es[i][j];
            }
        }
        ps[q][j] = s;
    }
    __syncthreads();
    if (tid < NN) rsv[tid] = 1.f / (ps[0][tid] + ps[1][tid] + ps[2][tid] + ps[3][tid]);
    __syncthreads();

    // fold 1/colsum into hs rows (att[i][j]*h[j] == es[i][j] * (rs[j]*h[j]))
    for (int idx = tid; idx < NN * 16; idx += 256) {
        int j = idx >> 4, d4 = idx & 15;
        float rs = rsv[j];
        float4 v = *(float4*)&hs[j][d4 * 4];
        v.x *= rs; v.y *= rs; v.z *= rs; v.w *= rs;
        *(float4*)&hs[j][d4 * 4] = v;
    }
    __syncthreads();

    // aggregation: thread (i = tid>>2, t = tid&3) -> output row i, d in [16t,16t+16)
    {
        int i = tid >> 2, t = tid & 3;
        float4 a0 = {0,0,0,0}, a1 = {0,0,0,0}, a2 = {0,0,0,0}, a3 = {0,0,0,0};
        if (i < NN) {
#pragma unroll 2
            for (int j = 0; j < NN; j++) {
                float e = es[i][j];
                const float* hr = &hs[j][t * 16];
                float4 h0 = *(const float4*)(hr);
                float4 h1 = *(const float4*)(hr + 4);
                float4 h2 = *(const float4*)(hr + 8);
                float4 h3 = *(const float4*)(hr + 12);
                a0.x += e * h0.x; a0.y += e * h0.y; a0.z += e * h0.z; a0.w += e * h0.w;
                a1.x += e * h1.x; a1.y += e * h1.y; a1.z += e * h1.z; a1.w += e * h1.w;
                a2.x += e * h2.x; a2.y += e * h2.y; a2.z += e * h2.z; a2.w += e * h2.w;
                a3.x += e * h3.x; a3.y += e * h3.y; a3.z += e * h3.z; a3.w += e * h3.w;
            }
            float* ob = &g_hx[(size_t)b * NN * HID + (size_t)i * HID + head * FOUT + t * 16];
            float r[16] = {a0.x,a0.y,a0.z,a0.w, a1.x,a1.y,a1.z,a1.w,
                           a2.x,a2.y,a2.z,a2.w, a3.x,a3.y,a3.z,a3.w};
#pragma unroll
            for (int q = 0; q < 16; q++) {
                float v = r[q];
                v = v > 0.f ? v : expm1f(v);   // ELU
                r[q] = tf32r(v);
            }
            *(float4*)(ob)      = make_float4(r[0],  r[1],  r[2],  r[3]);
            *(float4*)(ob + 4)  = make_float4(r[4],  r[5],  r[6],  r[7]);
            *(float4*)(ob + 8)  = make_float4(r[8],  r[9],  r[10], r[11]);
            *(float4*)(ob + 12) = make_float4(r[12], r[13], r[14], r[15]);
        }
    }
}

// ===========================================================================
// K5: pool + output head + log_softmax
// ===========================================================================
__global__ __launch_bounds__(512) void k5_out(
    const float* __restrict__ Wout, const float* __restrict__ bout,
    float* __restrict__ out)
{
    int b = blockIdx.x, tid = threadIdx.x;
    const float* hb = &g_hx[(size_t)b * NN * HID];
    float s = 0.f;
    for (int n = 0; n < NN; n++) s += hb[(size_t)n * HID + tid];

    __shared__ float red[512];
    __shared__ float lg[3];
    for (int c = 0; c < 3; c++) {
        red[tid] = s * Wout[tid * 3 + c];
        __syncthreads();
        for (int off = 256; off > 0; off >>= 1) {
            if (tid < off) red[tid] += red[tid + off];
            __syncthreads();
        }
        if (tid == 0) lg[c] = red[0] + bout[c];
        __syncthreads();
    }
    if (tid == 0) {
        float m = fmaxf(lg[0], fmaxf(lg[1], lg[2]));
        float sum = expf(lg[0] - m) + expf(lg[1] - m) + expf(lg[2] - m);
        float lse = logf(sum) + m;
        out[b * 3 + 0] = lg[0] - lse;
        out[b * 3 + 1] = lg[1] - lse;
        out[b * 3 + 2] = lg[2] - lse;
    }
}

// ===========================================================================
extern "C" void kernel_launch(void* const* d_in, const int* in_sizes, int n_in,
                              void* d_out, int out_size)
{
    const float* x     = (const float*)d_in[0];
    const int*   adj   = (const int*)  d_in[1];
    const float* gamma = (const float*)d_in[2];
    const float* beta  = (const float*)d_in[3];
    const float* mean  = (const float*)d_in[4];
    const float* var   = (const float*)d_in[5];
    const float* Wm    = (const float*)d_in[6];
    const float* bm    = (const float*)d_in[7];
    const float* Wg    = (const float*)d_in[8];
    const float* ag    = (const float*)d_in[9];
    const float* Wo    = (const float*)d_in[10];
    const float* bo    = (const float*)d_in[11];
    float* out = (float*)d_out;

    cudaFuncSetAttribute(k2_mma, cudaFuncAttributeMaxDynamicSharedMemorySize, K2_SMEM);

    k0_round_w<<<(3 * HEADS * HID * FOUT + 1023) / 1024, 1024>>>(Wg);
    k1_bn_mlp<<<NROWS / 8, 128>>>(x, gamma, beta, mean, var, Wm, bm);

    for (int l = 0; l < 3; l++) {
        k2_mma<<<dim3(HID / TN, NROWS / TM), 256, K2_SMEM>>>(l);
        k4_attn<<<dim3(BB, HEADS), 256>>>(adj, ag + (size_t)l * HEADS * 2 * FOUT);
    }

    k5_out<<<BB, 512>>>(Wo, bo, out);
}

// round 7
// speedup vs baseline: 1.3531x; 1.3531x over previous
#include <cuda_runtime.h>
#include <math.h>
#include <cstdint>

#define BB    2048
#define NN    62
#define FIN   128
#define HID   512
#define HEADS 8
#define FOUT  64
#define NROWS (BB * NN)   // 126976

// Scratch: features ping-pong between g_hx and g_h.
// g_h doubles as the tf32-rounded copy of x before layer-0 K2 overwrites it.
__device__ float g_hx[(size_t)NROWS * HID];
__device__ float g_h [(size_t)NROWS * HID];
__device__ float g_Wr[(size_t)3 * HEADS * HID * FOUT];
__device__ float g_Wmr[FIN * HID];
__device__ float g_cs[HID];

// ===========================================================================
// helpers
// ===========================================================================
__device__ __forceinline__ uint32_t smem_u32(const void* p) {
    uint32_t a;
    asm("{ .reg .u64 t; cvta.to.shared.u64 t, %1; cvt.u32.u64 %0, t; }"
        : "=r"(a) : "l"(p));
    return a;
}
__device__ __forceinline__ float tf32r(float x) {
    uint32_t u;
    asm("cvt.rna.tf32.f32 %0, %1;" : "=r"(u) : "f"(x));
    return __uint_as_float(u);
}
__device__ __forceinline__ void cp_async16(uint32_t dst, const void* src) {
    asm volatile("cp.async.cg.shared.global [%0], [%1], 16;"
                 :: "r"(dst), "l"(src) : "memory");
}
__device__ __forceinline__ void cp_commit() {
    asm volatile("cp.async.commit_group;" ::: "memory");
}
template <int N>
__device__ __forceinline__ void cp_wait() {
    asm volatile("cp.async.wait_group %0;" :: "n"(N) : "memory");
}
__device__ __forceinline__ void mma_tf32(float* c, const uint32_t* a, const uint32_t* b) {
    asm volatile(
        "mma.sync.aligned.m16n8k8.row.col.f32.tf32.tf32.f32 "
        "{%0,%1,%2,%3}, {%4,%5,%6,%7}, {%8,%9}, {%0,%1,%2,%3};"
        : "+f"(c[0]), "+f"(c[1]), "+f"(c[2]), "+f"(c[3])
        : "r"(a[0]), "r"(a[1]), "r"(a[2]), "r"(a[3]), "r"(b[0]), "r"(b[1]));
}

// ===========================================================================
// K0 kernels: tf32 rounding of operands (round-to-nearest)
// ===========================================================================
__global__ void k0_round_w(const float* __restrict__ Wg) {
    int i = blockIdx.x * 1024 + threadIdx.x;
    if (i < 3 * HEADS * HID * FOUT) g_Wr[i] = tf32r(Wg[i]);
}
__global__ void k0_round_x(const float* __restrict__ x) {
    size_t i = (size_t)blockIdx.x * 1024 + threadIdx.x;
    if (i < (size_t)NROWS * FIN) g_h[i] = tf32r(x[i]);
}
__global__ void k0_round_wm(const float* __restrict__ Wm) {
    int i = blockIdx.x * 1024 + threadIdx.x;
    if (i < FIN * HID) g_Wmr[i] = tf32r(Wm[i]);
}
__global__ void k0_colsum_wm() {
    int c = threadIdx.x;   // 512 threads
    float s = 0.f;
    for (int k = 0; k < FIN; k++) s += g_Wmr[k * HID + c];
    g_cs[c] = s;
}

// ===========================================================================
// shared GEMM tile config (K2 and K1M)
// ===========================================================================
#define TM 128
#define TN 128
#define KC 32
#define NBUF 4
#define A_STRIDE 36
#define B_STRIDE 136
#define A_BYTES (TM * A_STRIDE * 4)        // 18432
#define B_BYTES (KC * B_STRIDE * 4)        // 17408
#define STAGE_BYTES (A_BYTES + B_BYTES)    // 35840
#define K2_SMEM (NBUF * STAGE_BYTES)       // 143360

// ===========================================================================
// K1M (tf32 mma): h_x = s_row*(x @ Wm) + t_row*colsum(Wm) + b, tf32-rounded.
// A = tf32-rounded x living in g_h. K = 128 (NS = 4).
// ===========================================================================
__global__ __launch_bounds__(256, 1) void k1_mma(
    const float* __restrict__ gamma, const float* __restrict__ beta,
    const float* __restrict__ mean,  const float* __restrict__ var,
    const float* __restrict__ bm)
{
    extern __shared__ __align__(16) char smem[];
    const int NS_K = FIN / KC;   // 4
    const int tid  = threadIdx.x;
    const int lane = tid & 31;
    const int wid  = tid >> 5;
    const int wm   = wid & 3;
    const int wn   = wid >> 2;
    const int n0   = blockIdx.x * TN;
    const int row0 = blockIdx.y * TM;
    const uint32_t sbase = smem_u32(smem);

    auto issue_stage = [&](int s) {
        const int p = s & (NBUF - 1);
        const float* Ag = g_h + (size_t)row0 * FIN + s * KC;   // rounded x
        const uint32_t Ad = sbase + p * STAGE_BYTES;
#pragma unroll
        for (int i = 0; i < 4; i++) {
            int idx = tid + i * 256;
            int r = idx >> 3, k4 = idx & 7;
            cp_async16(Ad + r * (A_STRIDE * 4) + k4 * 16,
                       Ag + (size_t)r * FIN + k4 * 4);
        }
        const uint32_t Bd = sbase + p * STAGE_BYTES + A_BYTES;
#pragma unroll
        for (int i = 0; i < 4; i++) {
            int idx = tid + i * 256;
            int k = idx >> 5, n4 = idx & 31;
            cp_async16(Bd + k * (B_STRIDE * 4) + n4 * 16,
                       g_Wmr + (size_t)(s * KC + k) * HID + n0 + n4 * 4);
        }
    };

    float acc[2][8][4];
#pragma unroll
    for (int mt = 0; mt < 2; mt++)
#pragma unroll
        for (int nt = 0; nt < 8; nt++)
#pragma unroll
            for (int q = 0; q < 4; q++) acc[mt][nt][q] = 0.f;

#pragma unroll
    for (int s = 0; s < NBUF - 1; s++) { issue_stage(s); cp_commit(); }

#pragma unroll 1
    for (int s = 0; s < NS_K; s++) {
        if (s < NS_K - 2)       cp_wait<2>();
        else if (s == NS_K - 2) cp_wait<1>();
        else                    cp_wait<0>();
        __syncthreads();
        if (s + NBUF - 1 < NS_K) issue_stage(s + NBUF - 1);
        cp_commit();

        const float* As = (const float*)(smem + (s & (NBUF - 1)) * STAGE_BYTES);
        const float* Bs = As + TM * A_STRIDE;

#pragma unroll
        for (int ks = 0; ks < KC / 8; ks++) {
            const int kb = ks * 8;
            uint32_t a[2][4], b[8][2];
#pragma unroll
            for (int mt = 0; mt < 2; mt++) {
                int r = wm * 32 + mt * 16 + (lane >> 2);
                int k = kb + (lane & 3);
                a[mt][0] = __float_as_uint(As[r * A_STRIDE + k]);
                a[mt][1] = __float_as_uint(As[(r + 8) * A_STRIDE + k]);
                a[mt][2] = __float_as_uint(As[r * A_STRIDE + k + 4]);
                a[mt][3] = __float_as_uint(As[(r + 8) * A_STRIDE + k + 4]);
            }
#pragma unroll
            for (int nt = 0; nt < 8; nt++) {
                int c = wn * 64 + nt * 8 + (lane >> 2);
                int k = kb + (lane & 3);
                b[nt][0] = __float_as_uint(Bs[k * B_STRIDE + c]);
                b[nt][1] = __float_as_uint(Bs[(k + 4) * B_STRIDE + c]);
            }
#pragma unroll
            for (int mt = 0; mt < 2; mt++)
#pragma unroll
                for (int nt = 0; nt < 8; nt++)
                    mma_tf32(acc[mt][nt], a[mt], b[nt]);
        }
    }

    // epilogue: out = s[n]*acc + t[n]*cs[c] + bm[c], rounded to tf32
    const int rbase = wm * 32 + (lane >> 2);
    float sv[4], tv[4];
#pragma unroll
    for (int q = 0; q < 4; q++) {
        int r = row0 + rbase + q * 8;
        int n = r % NN;
        float sc = gamma[n] * rsqrtf(var[n] + 1e-5f);
        sv[q] = sc;
        tv[q] = beta[n] - mean[n] * sc;
    }
#pragma unroll
    for (int mt = 0; mt < 2; mt++) {
        int r = row0 + rbase + mt * 16;
#pragma unroll
        for (int nt = 0; nt < 8; nt++) {
            int c = n0 + wn * 64 + nt * 8 + 2 * (lane & 3);
            float cs0 = g_cs[c], cs1 = g_cs[c + 1];
            float b0 = bm[c], b1 = bm[c + 1];
            int q0 = mt * 2, q1 = mt * 2 + 1;
            *(float2*)&g_hx[(size_t)r * HID + c] = make_float2(
                tf32r(sv[q0] * acc[mt][nt][0] + tv[q0] * cs0 + b0),
                tf32r(sv[q0] * acc[mt][nt][1] + tv[q0] * cs1 + b1));
            *(float2*)&g_hx[(size_t)(r + 8) * HID + c] = make_float2(
                tf32r(sv[q1] * acc[mt][nt][2] + tv[q1] * cs0 + b0),
                tf32r(sv[q1] * acc[mt][nt][3] + tv[q1] * cs1 + b1));
        }
    }
}

// ===========================================================================
// K2 (tf32 mma.sync): g_h = g_hx @ W_gat[l]   (unchanged from Round 5)
// ===========================================================================
__global__ __launch_bounds__(256, 1) void k2_mma(int layer)
{
    extern __shared__ __align__(16) char smem[];
    const int NS_K = HID / KC;   // 16
    const int tid  = threadIdx.x;
    const int lane = tid & 31;
    const int wid  = tid >> 5;
    const int wm   = wid & 3;
    const int wn   = wid >> 2;
    const int n0   = blockIdx.x * TN;
    const int row0 = blockIdx.y * TM;
    const uint32_t sbase = smem_u32(smem);
    const float* Wl = g_Wr + (size_t)layer * HEADS * HID * FOUT;
    const float* Wb = Wl + (size_t)(n0 >> 6) * HID * FOUT;

    auto issue_stage = [&](int s) {
        const int p = s & (NBUF - 1);
        const float* Ag = g_hx + (size_t)row0 * HID + s * KC;
        const uint32_t Ad = sbase + p * STAGE_BYTES;
#pragma unroll
        for (int i = 0; i < 4; i++) {
            int idx = tid + i * 256;
            int r = idx >> 3, k4 = idx & 7;
            cp_async16(Ad + r * (A_STRIDE * 4) + k4 * 16,
                       Ag + (size_t)r * HID + k4 * 4);
        }
        const uint32_t Bd = sbase + p * STAGE_BYTES + A_BYTES;
#pragma unroll
        for (int i = 0; i < 4; i++) {
            int idx = tid + i * 256;
            int k = idx >> 5, n4 = idx & 31;
            int n = n4 * 4;
            const float* sp = Wb + (size_t)(n >> 6) * HID * FOUT
                                 + (size_t)(s * KC + k) * FOUT + (n & 63);
            cp_async16(Bd + k * (B_STRIDE * 4) + n4 * 16, sp);
        }
    };

    float acc[2][8][4];
#pragma unroll
    for (int mt = 0; mt < 2; mt++)
#pragma unroll
        for (int nt = 0; nt < 8; nt++)
#pragma unroll
            for (int q = 0; q < 4; q++) acc[mt][nt][q] = 0.f;

#pragma unroll
    for (int s = 0; s < NBUF - 1; s++) { issue_stage(s); cp_commit(); }

#pragma unroll 1
    for (int s = 0; s < NS_K; s++) {
        if (s < NS_K - 2)       cp_wait<2>();
        else if (s == NS_K - 2) cp_wait<1>();
        else                    cp_wait<0>();
        __syncthreads();
        if (s + NBUF - 1 < NS_K) issue_stage(s + NBUF - 1);
        cp_commit();

        const float* As = (const float*)(smem + (s & (NBUF - 1)) * STAGE_BYTES);
        const float* Bs = As + TM * A_STRIDE;

#pragma unroll
        for (int ks = 0; ks < KC / 8; ks++) {
            const int kb = ks * 8;
            uint32_t a[2][4], b[8][2];
#pragma unroll
            for (int mt = 0; mt < 2; mt++) {
                int r = wm * 32 + mt * 16 + (lane >> 2);
                int k = kb + (lane & 3);
                a[mt][0] = __float_as_uint(As[r * A_STRIDE + k]);
                a[mt][1] = __float_as_uint(As[(r + 8) * A_STRIDE + k]);
                a[mt][2] = __float_as_uint(As[r * A_STRIDE + k + 4]);
                a[mt][3] = __float_as_uint(As[(r + 8) * A_STRIDE + k + 4]);
            }
#pragma unroll
            for (int nt = 0; nt < 8; nt++) {
                int c = wn * 64 + nt * 8 + (lane >> 2);
                int k = kb + (lane & 3);
                b[nt][0] = __float_as_uint(Bs[k * B_STRIDE + c]);
                b[nt][1] = __float_as_uint(Bs[(k + 4) * B_STRIDE + c]);
            }
#pragma unroll
            for (int mt = 0; mt < 2; mt++)
#pragma unroll
                for (int nt = 0; nt < 8; nt++)
                    mma_tf32(acc[mt][nt], a[mt], b[nt]);
        }
    }

#pragma unroll
    for (int mt = 0; mt < 2; mt++) {
        int r = row0 + wm * 32 + mt * 16 + (lane >> 2);
#pragma unroll
        for (int nt = 0; nt < 8; nt++) {
            int c = n0 + wn * 64 + nt * 8 + 2 * (lane & 3);
            *(float2*)&g_h[(size_t)r * HID + c] =
                make_float2(acc[mt][nt][0], acc[mt][nt][1]);
            *(float2*)&g_h[(size_t)(r + 8) * HID + c] =
                make_float2(acc[mt][nt][2], acc[mt][nt][3]);
        }
    }
}

// ===========================================================================
// K4: per-(batch, head) attention block — Round-5 version (known 659us)
// ===========================================================================
__global__ __launch_bounds__(256) void k4_attn(
    const int* __restrict__ adj, const float* __restrict__ a_l)
{
    __shared__ float hs[64][FOUT + 1];
    __shared__ float es[64][NN + 1];
    __shared__ float asv[2 * FOUT];
    __shared__ float f1[NN], f2[NN];
    __shared__ float pm[4][64], ps[4][64];

    int b    = blockIdx.x;
    int head = blockIdx.y;
    int tid  = threadIdx.x;

    const float* hbase = &g_h[(size_t)b * NN * HID + head * FOUT];
    for (int idx = tid; idx < NN * FOUT; idx += 256) {
        int j = idx >> 6, d = idx & 63;
        hs[j][d] = hbase[(size_t)j * HID + d];
    }
    if (tid < 2 * FOUT) asv[tid] = a_l[head * 2 * FOUT + tid];
    if (tid < 2 * (NN + 1)) es[NN + tid / (NN + 1)][tid % (NN + 1)] = 0.f;
    if (tid < 2 * (FOUT + 1)) hs[NN + tid / (FOUT + 1)][tid % (FOUT + 1)] = 0.f;
    __syncthreads();

    {
        int node = tid >> 2, t = tid & 3;
        float s1 = 0.f, s2 = 0.f;
#pragma unroll
        for (int dd = 0; dd < 16; dd++) {
            int d = t * 16 + dd;
            float v = hs[node][d];
            s1 += v * asv[d];
            s2 += v * asv[FOUT + d];
        }
        s1 += __shfl_xor_sync(0xffffffffu, s1, 1);
        s1 += __shfl_xor_sync(0xffffffffu, s1, 2);
        s2 += __shfl_xor_sync(0xffffffffu, s2, 1);
        s2 += __shfl_xor_sync(0xffffffffu, s2, 2);
        if (t == 0 && node < NN) { f1[node] = s1; f2[node] = s2; }
    }
    __syncthreads();

    const int* adjb = adj + (size_t)b * NN * NN;
    for (int idx = tid; idx < NN * NN; idx += 256) {
        int i = idx / NN, j = idx - i * NN;
        float v = f2[i] + f1[j];
        v = v > 0.f ? v : 0.2f * v;
        if (adjb[idx] <= 0) v = -9e15f;
        es[i][j] = v;
    }
    __syncthreads();

    {
        int j = tid & 63, q = tid >> 6;
        float m = -3.4e38f;
        if (j < NN) {
#pragma unroll
            for (int ii = 0; ii < 16; ii++) {
                int i = q + ii * 4;
                if (i < NN) m = fmaxf(m, es[i][j]);
            }
        }
        pm[q][j] = m;
        __syncthreads();
        float M = fmaxf(fmaxf(pm[0][j], pm[1][j]), fmaxf(pm[2][j], pm[3][j]));
        float s = 0.f;
        if (j < NN) {
#pragma unroll
            for (int ii = 0; ii < 16; ii++) {
                int i = q + ii * 4;
                if (i < NN) {
                    float e = __expf(es[i][j] - M);
                    es[i][j] = e;
                    s += e;
                }
            }
        }
        ps[q][j] = s;
        __syncthreads();
        float rs = 1.f / (ps[0][j] + ps[1][j] + ps[2][j] + ps[3][j]);
        if (j < NN) {
#pragma unroll
            for (int ii = 0; ii < 16; ii++) {
                int i = q + ii * 4;
                if (i < NN) es[i][j] *= rs;
            }
        }
    }
    __syncthreads();

    int d  = tid & 63;
    int ig = tid >> 6;
    float acc[16];
#pragma unroll
    for (int ii = 0; ii < 16; ii++) acc[ii] = 0.f;

    for (int j = 0; j < NN; j++) {
        float hv = hs[j][d];
#pragma unroll
        for (int ii = 0; ii < 16; ii++) {
            acc[ii] += es[ig + ii * 4][j] * hv;
        }
    }

    float* outb = &g_hx[(size_t)b * NN * HID + head * FOUT + d];
#pragma unroll
    for (int ii = 0; ii < 16; ii++) {
        int i = ig + ii * 4;
        if (i < NN) {
            float v = acc[ii];
            v = v > 0.f ? v : expm1f(v);
            outb[(size_t)i * HID] = tf32r(v);
        }
    }
}

// ===========================================================================
// K5: pool + output head + log_softmax (warp-shuffle reductions)
// ===========================================================================
__global__ __launch_bounds__(512) void k5_out(
    const float* __restrict__ Wout, const float* __restrict__ bout,
    float* __restrict__ out)
{
    int b = blockIdx.x, tid = threadIdx.x;
    int lane = tid & 31, wid = tid >> 5;
    const float* hb = &g_hx[(size_t)b * NN * HID];
    float s = 0.f;
    for (int n = 0; n < NN; n++) s += hb[(size_t)n * HID + tid];

    float v0 = s * Wout[tid * 3 + 0];
    float v1 = s * Wout[tid * 3 + 1];
    float v2 = s * Wout[tid * 3 + 2];
#pragma unroll
    for (int off = 16; off > 0; off >>= 1) {
        v0 += __shfl_down_sync(0xffffffffu, v0, off);
        v1 += __shfl_down_sync(0xffffffffu, v1, off);
        v2 += __shfl_down_sync(0xffffffffu, v2, off);
    }
    __shared__ float red[3][16];
    if (lane == 0) { red[0][wid] = v0; red[1][wid] = v1; red[2][wid] = v2; }
    __syncthreads();
    if (tid == 0) {
        float lg[3];
#pragma unroll
        for (int c = 0; c < 3; c++) {
            float t = 0.f;
#pragma unroll
            for (int w = 0; w < 16; w++) t += red[c][w];
            lg[c] = t + bout[c];
        }
        float m = fmaxf(lg[0], fmaxf(lg[1], lg[2]));
        float sum = expf(lg[0] - m) + expf(lg[1] - m) + expf(lg[2] - m);
        float lse = logf(sum) + m;
        out[b * 3 + 0] = lg[0] - lse;
        out[b * 3 + 1] = lg[1] - lse;
        out[b * 3 + 2] = lg[2] - lse;
    }
}

// ===========================================================================
extern "C" void kernel_launch(void* const* d_in, const int* in_sizes, int n_in,
                              void* d_out, int out_size)
{
    const float* x     = (const float*)d_in[0];
    const int*   adj   = (const int*)  d_in[1];
    const float* gamma = (const float*)d_in[2];
    const float* beta  = (const float*)d_in[3];
    const float* mean  = (const float*)d_in[4];
    const float* var   = (const float*)d_in[5];
    const float* Wm    = (const float*)d_in[6];
    const float* bm    = (const float*)d_in[7];
    const float* Wg    = (const float*)d_in[8];
    const float* ag    = (const float*)d_in[9];
    const float* Wo    = (const float*)d_in[10];
    const float* bo    = (const float*)d_in[11];
    float* out = (float*)d_out;

    cudaFuncSetAttribute(k2_mma, cudaFuncAttributeMaxDynamicSharedMemorySize, K2_SMEM);
    cudaFuncSetAttribute(k1_mma, cudaFuncAttributeMaxDynamicSharedMemorySize, K2_SMEM);

    k0_round_w<<<(3 * HEADS * HID * FOUT + 1023) / 1024, 1024>>>(Wg);
    k0_round_wm<<<(FIN * HID + 1023) / 1024, 1024>>>(Wm);
    k0_colsum_wm<<<1, HID>>>();
    k0_round_x<<<(int)(((size_t)NROWS * FIN + 1023) / 1024), 1024>>>(x);

    k1_mma<<<dim3(HID / TN, NROWS / TM), 256, K2_SMEM>>>(gamma, beta, mean, var, bm);

    for (int l = 0; l < 3; l++) {
        k2_mma<<<dim3(HID / TN, NROWS / TM), 256, K2_SMEM>>>(l);
        k4_attn<<<dim3(BB, HEADS), 256>>>(adj, ag + (size_t)l * HEADS * 2 * FOUT);
    }

    k5_out<<<BB, 512>>>(Wo, bo, out);
}

// round 8
// speedup vs baseline: 1.7732x; 1.3105x over previous
#include <cuda_runtime.h>
#include <math.h>
#include <cstdint>

#define BB    2048
#define NN    62
#define FIN   128
#define HID   512
#define HEADS 8
#define FOUT  64
#define NROWS (BB * NN)   // 126976

__device__ float g_hx[(size_t)NROWS * HID];
__device__ float g_h [(size_t)NROWS * HID];
__device__ float g_Wr[(size_t)3 * HEADS * HID * FOUT];
__device__ float g_Wmr[FIN * HID];
__device__ float g_cs[HID];

// ===========================================================================
// helpers
// ===========================================================================
__device__ __forceinline__ uint32_t smem_u32(const void* p) {
    uint32_t a;
    asm("{ .reg .u64 t; cvta.to.shared.u64 t, %1; cvt.u32.u64 %0, t; }"
        : "=r"(a) : "l"(p));
    return a;
}
__device__ __forceinline__ float tf32r(float x) {
    uint32_t u;
    asm("cvt.rna.tf32.f32 %0, %1;" : "=r"(u) : "f"(x));
    return __uint_as_float(u);
}
__device__ __forceinline__ void cp_async16(uint32_t dst, const void* src) {
    asm volatile("cp.async.cg.shared.global [%0], [%1], 16;"
                 :: "r"(dst), "l"(src) : "memory");
}
__device__ __forceinline__ void cp_commit() {
    asm volatile("cp.async.commit_group;" ::: "memory");
}
template <int N>
__device__ __forceinline__ void cp_wait() {
    asm volatile("cp.async.wait_group %0;" :: "n"(N) : "memory");
}
__device__ __forceinline__ void mma_tf32(float* c, const uint32_t* a, const uint32_t* b) {
    asm volatile(
        "mma.sync.aligned.m16n8k8.row.col.f32.tf32.tf32.f32 "
        "{%0,%1,%2,%3}, {%4,%5,%6,%7}, {%8,%9}, {%0,%1,%2,%3};"
        : "+f"(c[0]), "+f"(c[1]), "+f"(c[2]), "+f"(c[3])
        : "r"(a[0]), "r"(a[1]), "r"(a[2]), "r"(a[3]), "r"(b[0]), "r"(b[1]));
}

// ===========================================================================
// K0 kernels: tf32 rounding of operands
// ===========================================================================
__global__ void k0_round_w(const float* __restrict__ Wg) {
    int i = blockIdx.x * 1024 + threadIdx.x;
    if (i < 3 * HEADS * HID * FOUT) g_Wr[i] = tf32r(Wg[i]);
}
__global__ void k0_round_x(const float* __restrict__ x) {
    size_t i = ((size_t)blockIdx.x * 256 + threadIdx.x) * 4;
    float4 v = *(const float4*)(x + i);
    v.x = tf32r(v.x); v.y = tf32r(v.y); v.z = tf32r(v.z); v.w = tf32r(v.w);
    *(float4*)(g_h + i) = v;
}
__global__ void k0_round_wm(const float* __restrict__ Wm) {
    int i = blockIdx.x * 1024 + threadIdx.x;
    if (i < FIN * HID) g_Wmr[i] = tf32r(Wm[i]);
}
__global__ void k0_colsum_wm() {
    int c = threadIdx.x;
    float s = 0.f;
    for (int k = 0; k < FIN; k++) s += g_Wmr[k * HID + c];
    g_cs[c] = s;
}

// ===========================================================================
// shared GEMM tile config (K1M / K2)
// ===========================================================================
#define TM 128
#define TN 128
#define KC 32
#define NBUF 4
#define A_STRIDE 36
#define B_STRIDE 136
#define A_BYTES (TM * A_STRIDE * 4)
#define B_BYTES (KC * B_STRIDE * 4)
#define STAGE_BYTES (A_BYTES + B_BYTES)
#define K2_SMEM (NBUF * STAGE_BYTES)

// ===========================================================================
// K1M (tf32 mma): h_x = s_row*(x @ Wm) + t_row*colsum(Wm) + b
// ===========================================================================
__global__ __launch_bounds__(256, 1) void k1_mma(
    const float* __restrict__ gamma, const float* __restrict__ beta,
    const float* __restrict__ mean,  const float* __restrict__ var,
    const float* __restrict__ bm)
{
    extern __shared__ __align__(16) char smem[];
    const int NS_K = FIN / KC;   // 4
    const int tid  = threadIdx.x;
    const int lane = tid & 31;
    const int wid  = tid >> 5;
    const int wm   = wid & 3;
    const int wn   = wid >> 2;
    const int n0   = blockIdx.x * TN;
    const int row0 = blockIdx.y * TM;
    const uint32_t sbase = smem_u32(smem);

    auto issue_stage = [&](int s) {
        const int p = s & (NBUF - 1);
        const float* Ag = g_h + (size_t)row0 * FIN + s * KC;
        const uint32_t Ad = sbase + p * STAGE_BYTES;
#pragma unroll
        for (int i = 0; i < 4; i++) {
            int idx = tid + i * 256;
            int r = idx >> 3, k4 = idx & 7;
            cp_async16(Ad + r * (A_STRIDE * 4) + k4 * 16,
                       Ag + (size_t)r * FIN + k4 * 4);
        }
        const uint32_t Bd = sbase + p * STAGE_BYTES + A_BYTES;
#pragma unroll
        for (int i = 0; i < 4; i++) {
            int idx = tid + i * 256;
            int k = idx >> 5, n4 = idx & 31;
            cp_async16(Bd + k * (B_STRIDE * 4) + n4 * 16,
                       g_Wmr + (size_t)(s * KC + k) * HID + n0 + n4 * 4);
        }
    };

    float acc[2][8][4];
#pragma unroll
    for (int mt = 0; mt < 2; mt++)
#pragma unroll
        for (int nt = 0; nt < 8; nt++)
#pragma unroll
            for (int q = 0; q < 4; q++) acc[mt][nt][q] = 0.f;

#pragma unroll
    for (int s = 0; s < NBUF - 1; s++) { issue_stage(s); cp_commit(); }

#pragma unroll 1
    for (int s = 0; s < NS_K; s++) {
        if (s < NS_K - 2)       cp_wait<2>();
        else if (s == NS_K - 2) cp_wait<1>();
        else                    cp_wait<0>();
        __syncthreads();
        if (s + NBUF - 1 < NS_K) issue_stage(s + NBUF - 1);
        cp_commit();

        const float* As = (const float*)(smem + (s & (NBUF - 1)) * STAGE_BYTES);
        const float* Bs = As + TM * A_STRIDE;

#pragma unroll
        for (int ks = 0; ks < KC / 8; ks++) {
            const int kb = ks * 8;
            uint32_t a[2][4], b[8][2];
#pragma unroll
            for (int mt = 0; mt < 2; mt++) {
                int r = wm * 32 + mt * 16 + (lane >> 2);
                int k = kb + (lane & 3);
                a[mt][0] = __float_as_uint(As[r * A_STRIDE + k]);
                a[mt][1] = __float_as_uint(As[(r + 8) * A_STRIDE + k]);
                a[mt][2] = __float_as_uint(As[r * A_STRIDE + k + 4]);
                a[mt][3] = __float_as_uint(As[(r + 8) * A_STRIDE + k + 4]);
            }
#pragma unroll
            for (int nt = 0; nt < 8; nt++) {
                int c = wn * 64 + nt * 8 + (lane >> 2);
                int k = kb + (lane & 3);
                b[nt][0] = __float_as_uint(Bs[k * B_STRIDE + c]);
                b[nt][1] = __float_as_uint(Bs[(k + 4) * B_STRIDE + c]);
            }
#pragma unroll
            for (int mt = 0; mt < 2; mt++)
#pragma unroll
                for (int nt = 0; nt < 8; nt++)
                    mma_tf32(acc[mt][nt], a[mt], b[nt]);
        }
    }

    const int rbase = wm * 32 + (lane >> 2);
    float sv[4], tv[4];
#pragma unroll
    for (int q = 0; q < 4; q++) {
        int r = row0 + rbase + q * 8;
        int n = r % NN;
        float sc = gamma[n] * rsqrtf(var[n] + 1e-5f);
        sv[q] = sc;
        tv[q] = beta[n] - mean[n] * sc;
    }
#pragma unroll
    for (int mt = 0; mt < 2; mt++) {
        int r = row0 + rbase + mt * 16;
#pragma unroll
        for (int nt = 0; nt < 8; nt++) {
            int c = n0 + wn * 64 + nt * 8 + 2 * (lane & 3);
            float cs0 = g_cs[c], cs1 = g_cs[c + 1];
            float b0 = bm[c], b1 = bm[c + 1];
            int q0 = mt * 2, q1 = mt * 2 + 1;
            *(float2*)&g_hx[(size_t)r * HID + c] = make_float2(
                tf32r(sv[q0] * acc[mt][nt][0] + tv[q0] * cs0 + b0),
                tf32r(sv[q0] * acc[mt][nt][1] + tv[q0] * cs1 + b1));
            *(float2*)&g_hx[(size_t)(r + 8) * HID + c] = make_float2(
                tf32r(sv[q1] * acc[mt][nt][2] + tv[q1] * cs0 + b0),
                tf32r(sv[q1] * acc[mt][nt][3] + tv[q1] * cs1 + b1));
        }
    }
}

// ===========================================================================
// K2 (tf32 mma): g_h = g_hx @ W_gat[l]
// ===========================================================================
__global__ __launch_bounds__(256, 1) void k2_mma(int layer)
{
    extern __shared__ __align__(16) char smem[];
    const int NS_K = HID / KC;   // 16
    const int tid  = threadIdx.x;
    const int lane = tid & 31;
    const int wid  = tid >> 5;
    const int wm   = wid & 3;
    const int wn   = wid >> 2;
    const int n0   = blockIdx.x * TN;
    const int row0 = blockIdx.y * TM;
    const uint32_t sbase = smem_u32(smem);
    const float* Wl = g_Wr + (size_t)layer * HEADS * HID * FOUT;
    const float* Wb = Wl + (size_t)(n0 >> 6) * HID * FOUT;

    auto issue_stage = [&](int s) {
        const int p = s & (NBUF - 1);
        const float* Ag = g_hx + (size_t)row0 * HID + s * KC;
        const uint32_t Ad = sbase + p * STAGE_BYTES;
#pragma unroll
        for (int i = 0; i < 4; i++) {
            int idx = tid + i * 256;
            int r = idx >> 3, k4 = idx & 7;
            cp_async16(Ad + r * (A_STRIDE * 4) + k4 * 16,
                       Ag + (size_t)r * HID + k4 * 4);
        }
        const uint32_t Bd = sbase + p * STAGE_BYTES + A_BYTES;
#pragma unroll
        for (int i = 0; i < 4; i++) {
            int idx = tid + i * 256;
            int k = idx >> 5, n4 = idx & 31;
            int n = n4 * 4;
            const float* sp = Wb + (size_t)(n >> 6) * HID * FOUT
                                 + (size_t)(s * KC + k) * FOUT + (n & 63);
            cp_async16(Bd + k * (B_STRIDE * 4) + n4 * 16, sp);
        }
    };

    float acc[2][8][4];
#pragma unroll
    for (int mt = 0; mt < 2; mt++)
#pragma unroll
        for (int nt = 0; nt < 8; nt++)
#pragma unroll
            for (int q = 0; q < 4; q++) acc[mt][nt][q] = 0.f;

#pragma unroll
    for (int s = 0; s < NBUF - 1; s++) { issue_stage(s); cp_commit(); }

#pragma unroll 1
    for (int s = 0; s < NS_K; s++) {
        if (s < NS_K - 2)       cp_wait<2>();
        else if (s == NS_K - 2) cp_wait<1>();
        else                    cp_wait<0>();
        __syncthreads();
        if (s + NBUF - 1 < NS_K) issue_stage(s + NBUF - 1);
        cp_commit();

        const float* As = (const float*)(smem + (s & (NBUF - 1)) * STAGE_BYTES);
        const float* Bs = As + TM * A_STRIDE;

#pragma unroll
        for (int ks = 0; ks < KC / 8; ks++) {
            const int kb = ks * 8;
            uint32_t a[2][4], b[8][2];
#pragma unroll
            for (int mt = 0; mt < 2; mt++) {
                int r = wm * 32 + mt * 16 + (lane >> 2);
                int k = kb + (lane & 3);
                a[mt][0] = __float_as_uint(As[r * A_STRIDE + k]);
                a[mt][1] = __float_as_uint(As[(r + 8) * A_STRIDE + k]);
                a[mt][2] = __float_as_uint(As[r * A_STRIDE + k + 4]);
                a[mt][3] = __float_as_uint(As[(r + 8) * A_STRIDE + k + 4]);
            }
#pragma unroll
            for (int nt = 0; nt < 8; nt++) {
                int c = wn * 64 + nt * 8 + (lane >> 2);
                int k = kb + (lane & 3);
                b[nt][0] = __float_as_uint(Bs[k * B_STRIDE + c]);
                b[nt][1] = __float_as_uint(Bs[(k + 4) * B_STRIDE + c]);
            }
#pragma unroll
            for (int mt = 0; mt < 2; mt++)
#pragma unroll
                for (int nt = 0; nt < 8; nt++)
                    mma_tf32(acc[mt][nt], a[mt], b[nt]);
        }
    }

#pragma unroll
    for (int mt = 0; mt < 2; mt++) {
        int r = row0 + wm * 32 + mt * 16 + (lane >> 2);
#pragma unroll
        for (int nt = 0; nt < 8; nt++) {
            int c = n0 + wn * 64 + nt * 8 + 2 * (lane & 3);
            *(float2*)&g_h[(size_t)r * HID + c] =
                make_float2(acc[mt][nt][0], acc[mt][nt][1]);
            *(float2*)&g_h[(size_t)(r + 8) * HID + c] =
                make_float2(acc[mt][nt][2], acc[mt][nt][3]);
        }
    }
}

// ===========================================================================
// K4: per-(batch, head) attention. Aggregation hp = att @ h done on tensor
// cores: 64x64x64 tf32 mma (pads zeroed). 1/colsum folded into hs rows.
// es stride 68 -> a-frag banks 4r+k all distinct; hs stride 72 -> b-frag
// banks 8k+c all distinct (both conflict-free).
// ===========================================================================
#define HS_STR 72
#define ES_STR 68

__global__ __launch_bounds__(256) void k4_attn(
    const int* __restrict__ adj, const float* __restrict__ a_l)
{
    __shared__ float hs[64][HS_STR];
    __shared__ float es[64][ES_STR];
    __shared__ float asv[2 * FOUT];
    __shared__ float f1[64], f2[64];
    __shared__ float ps[4][64];
    __shared__ float rsv[64];

    const int b    = blockIdx.x;
    const int head = blockIdx.y;
    const int tid  = threadIdx.x;
    const int lane = tid & 31;
    const int wid  = tid >> 5;

    // load h tile (zero pad rows 62,63)
    const float* hbase = &g_h[(size_t)b * NN * HID + head * FOUT];
    for (int idx = tid; idx < 64 * 16; idx += 256) {
        int j = idx >> 4, d4 = idx & 15;
        float4 v = (j < NN) ? *(const float4*)(hbase + (size_t)j * HID + d4 * 4)
                            : make_float4(0.f, 0.f, 0.f, 0.f);
        *(float4*)&hs[j][d4 * 4] = v;
    }
    if (tid < 2 * FOUT) asv[tid] = a_l[head * 2 * FOUT + tid];
    __syncthreads();

    // f1/f2: 4 threads per node, quad shfl reduce
    {
        int node = tid >> 2, t = tid & 3;
        float s1 = 0.f, s2 = 0.f;
#pragma unroll
        for (int dd = 0; dd < 16; dd++) {
            int d = t * 16 + dd;
            float v = hs[node][d];
            s1 += v * asv[d];
            s2 += v * asv[FOUT + d];
        }
        s1 += __shfl_xor_sync(0xffffffffu, s1, 1);
        s1 += __shfl_xor_sync(0xffffffffu, s1, 2);
        s2 += __shfl_xor_sync(0xffffffffu, s2, 1);
        s2 += __shfl_xor_sync(0xffffffffu, s2, 2);
        if (t == 0) { f1[node] = s1; f2[node] = s2; }
    }
    __syncthreads();

    // es[i][j] = tf32r(exp(leaky(f2[i]+f1[j]))) masked; pads (i or j >=62) = 0
    const int* adjb = adj + (size_t)b * NN * NN;
    for (int idx = tid; idx < 64 * 64; idx += 256) {
        int i = idx >> 6, j = idx & 63;
        float e = 0.f;
        if (i < NN && j < NN && adjb[i * NN + j] > 0) {
            float v = f2[i] + f1[j];
            v = v > 0.f ? v : 0.2f * v;
            e = tf32r(__expf(v));
        }
        es[i][j] = e;
    }
    __syncthreads();

    // column sums over i (softmax axis), 4 threads per column
    {
        int j = tid & 63, q = tid >> 6;
        float s = 0.f;
#pragma unroll
        for (int ii = 0; ii < 16; ii++) s += es[q + ii * 4][j];
        ps[q][j] = s;
    }
    __syncthreads();
    if (tid < 64) {
        float s = ps[0][tid] + ps[1][tid] + ps[2][tid] + ps[3][tid];
        rsv[tid] = (s > 0.f) ? 1.f / s : 0.f;
    }
    __syncthreads();

    // fold 1/colsum[j] into hs row j, round to tf32
    for (int idx = tid; idx < 64 * 16; idx += 256) {
        int j = idx >> 4, d4 = idx & 15;
        float rs = rsv[j];
        float4 v = *(float4*)&hs[j][d4 * 4];
        v.x = tf32r(v.x * rs); v.y = tf32r(v.y * rs);
        v.z = tf32r(v.z * rs); v.w = tf32r(v.w * rs);
        *(float4*)&hs[j][d4 * 4] = v;
    }
    __syncthreads();

    // tensor-core aggregation: D[64x64] = es[64x64] @ hs[64x64]
    // warps: 4 along M (16 rows) x 2 along N (32 cols)
    {
        const int wm = wid & 3, wn = wid >> 2;
        float acc[4][4];
#pragma unroll
        for (int nt = 0; nt < 4; nt++)
#pragma unroll
            for (int q = 0; q < 4; q++) acc[nt][q] = 0.f;

        const int r = wm * 16 + (lane >> 2);
#pragma unroll
        for (int kb = 0; kb < 64; kb += 8) {
            const int k = kb + (lane & 3);
            uint32_t a[4];
            a[0] = __float_as_uint(es[r][k]);
            a[1] = __float_as_uint(es[r + 8][k]);
            a[2] = __float_as_uint(es[r][k + 4]);
            a[3] = __float_as_uint(es[r + 8][k + 4]);
#pragma unroll
            for (int nt = 0; nt < 4; nt++) {
                const int c = wn * 32 + nt * 8 + (lane >> 2);
                uint32_t bb[2];
                bb[0] = __float_as_uint(hs[k][c]);
                bb[1] = __float_as_uint(hs[k + 4][c]);
                mma_tf32(acc[nt], a, bb);
            }
        }

        // epilogue: ELU + tf32 round + store (skip pad rows 62,63)
        const int i0 = wm * 16 + (lane >> 2);
        const int i1 = i0 + 8;
        float* ob = &g_hx[(size_t)b * NN * HID + head * FOUT];
#pragma unroll
        for (int nt = 0; nt < 4; nt++) {
            int c = wn * 32 + nt * 8 + 2 * (lane & 3);
            float v0 = acc[nt][0], v1 = acc[nt][1];
            v0 = v0 > 0.f ? v0 : expm1f(v0);
            v1 = v1 > 0.f ? v1 : expm1f(v1);
            *(float2*)(ob + (size_t)i0 * HID + c) =
                make_float2(tf32r(v0), tf32r(v1));
            if (i1 < NN) {
                float v2 = acc[nt][2], v3 = acc[nt][3];
                v2 = v2 > 0.f ? v2 : expm1f(v2);
                v3 = v3 > 0.f ? v3 : expm1f(v3);
                *(float2*)(ob + (size_t)i1 * HID + c) =
                    make_float2(tf32r(v2), tf32r(v3));
            }
        }
    }
}

// ===========================================================================
// K5: pool + output head + log_softmax (warp-shuffle reductions)
// ===========================================================================
__global__ __launch_bounds__(512) void k5_out(
    const float* __restrict__ Wout, const float* __restrict__ bout,
    float* __restrict__ out)
{
    int b = blockIdx.x, tid = threadIdx.x;
    int lane = tid & 31, wid = tid >> 5;
    const float* hb = &g_hx[(size_t)b * NN * HID];
    float s = 0.f;
    for (int n = 0; n < NN; n++) s += hb[(size_t)n * HID + tid];

    float v0 = s * Wout[tid * 3 + 0];
    float v1 = s * Wout[tid * 3 + 1];
    float v2 = s * Wout[tid * 3 + 2];
#pragma unroll
    for (int off = 16; off > 0; off >>= 1) {
        v0 += __shfl_down_sync(0xffffffffu, v0, off);
        v1 += __shfl_down_sync(0xffffffffu, v1, off);
        v2 += __shfl_down_sync(0xffffffffu, v2, off);
    }
    __shared__ float red[3][16];
    if (lane == 0) { red[0][wid] = v0; red[1][wid] = v1; red[2][wid] = v2; }
    __syncthreads();
    if (tid == 0) {
        float lg[3];
#pragma unroll
        for (int c = 0; c < 3; c++) {
            float t = 0.f;
#pragma unroll
            for (int w = 0; w < 16; w++) t += red[c][w];
            lg[c] = t + bout[c];
        }
        float m = fmaxf(lg[0], fmaxf(lg[1], lg[2]));
        float sum = expf(lg[0] - m) + expf(lg[1] - m) + expf(lg[2] - m);
        float lse = logf(sum) + m;
        out[b * 3 + 0] = lg[0] - lse;
        out[b * 3 + 1] = lg[1] - lse;
        out[b * 3 + 2] = lg[2] - lse;
    }
}

// ===========================================================================
extern "C" void kernel_launch(void* const* d_in, const int* in_sizes, int n_in,
                              void* d_out, int out_size)
{
    const float* x     = (const float*)d_in[0];
    const int*   adj   = (const int*)  d_in[1];
    const float* gamma = (const float*)d_in[2];
    const float* beta  = (const float*)d_in[3];
    const float* mean  = (const float*)d_in[4];
    const float* var   = (const float*)d_in[5];
    const float* Wm    = (const float*)d_in[6];
    const float* bm    = (const float*)d_in[7];
    const float* Wg    = (const float*)d_in[8];
    const float* ag    = (const float*)d_in[9];
    const float* Wo    = (const float*)d_in[10];
    const float* bo    = (const float*)d_in[11];
    float* out = (float*)d_out;

    cudaFuncSetAttribute(k2_mma, cudaFuncAttributeMaxDynamicSharedMemorySize, K2_SMEM);
    cudaFuncSetAttribute(k1_mma, cudaFuncAttributeMaxDynamicSharedMemorySize, K2_SMEM);

    k0_round_w<<<(3 * HEADS * HID * FOUT + 1023) / 1024, 1024>>>(Wg);
    k0_round_wm<<<(FIN * HID + 1023) / 1024, 1024>>>(Wm);
    k0_colsum_wm<<<1, HID>>>();
    k0_round_x<<<(int)(((size_t)NROWS * FIN) / 1024), 256>>>(x);

    k1_mma<<<dim3(HID / TN, NROWS / TM), 256, K2_SMEM>>>(gamma, beta, mean, var, bm);

    for (int l = 0; l < 3; l++) {
        k2_mma<<<dim3(HID / TN, NROWS / TM), 256, K2_SMEM>>>(l);
        k4_attn<<<dim3(BB, HEADS), 256>>>(adj, ag + (size_t)l * HEADS * 2 * FOUT);
    }

    k5_out<<<BB, 512>>>(Wo, bo, out);
}